// round 8
// baseline (speedup 1.0000x reference)
#include <cuda_runtime.h>
#include <cuda_bf16.h>

#define N_VERTS 262144
#define N_PAIRS 8388608
#define NW      52429        // ceil(N_VERTS/5) packed words, 6 bits/vertex
#define NWPAD   52432        // padded to /4 for int4 staging
#define DHAT2   0.0025f
#define EPSF    1e-12f
// Conservative threshold in cell^2 units (cell = 0.125): true bound 3.76;
// use 61/16 = 3.8125. Tests: 16*ap2<61, 16*bp2<61, 16*cr^2<61*den.

__device__ float2   g_coords[N_VERTS];   // 2 MB, L2-resident
__device__ unsigned g_qtab[NWPAD];       // 6-bit quantized coords, 5/word

// ---------------------------------------------------------------- setup
__global__ void setup_kernel(const float* __restrict__ Uu,
                             const float* __restrict__ rest,
                             float* __restrict__ out) {
    int w = blockIdx.x * blockDim.x + threadIdx.x;
    if (w >= NWPAD) return;
    const float2* Uu2   = reinterpret_cast<const float2*>(Uu);
    const float2* rest2 = reinterpret_cast<const float2*>(rest);
    unsigned packed = 0;
    int base = w * 5;
    #pragma unroll
    for (int k = 0; k < 5; k++) {
        int vi = base + k;
        if (vi < N_VERTS) {
            float2 u = __ldg(&Uu2[vi]);
            float2 r = __ldg(&rest2[vi]);
            float2 c = make_float2(u.x + r.x, u.y + r.y);
            g_coords[vi] = c;
            int qx = min(7, max(0, (int)(c.x * 8.0f)));
            int qy = min(7, max(0, (int)(c.y * 8.0f)));
            packed |= (unsigned)(qx | (qy << 3)) << (6 * k);
        }
    }
    g_qtab[w] = packed;
    if (w == 0) *out = 0.0f;
}

// ---------------------------------------------------------------- helpers
__device__ __forceinline__ unsigned qcode(const unsigned* __restrict__ s, int v) {
    unsigned w = (unsigned)v / 5u;
    unsigned r = (unsigned)v - w * 5u;
    return (s[w] >> (r * 6u)) & 63u;
}

__device__ __forceinline__ bool cell_filter(unsigned cp, unsigned ca, unsigned cb) {
    int px = cp & 7, py = (int)(cp >> 3);
    int ax = ca & 7, ay = (int)(ca >> 3);
    int bx = cb & 7, by = (int)(cb >> 3);
    int abx = bx - ax, aby = by - ay;
    int apx = px - ax, apy = py - ay;
    int den = abx * abx + aby * aby;
    int num = apx * abx + apy * aby;
    int ap2 = apx * apx + apy * apy;
    int bp2 = ap2 - 2 * num + den;
    int cr  = apx * aby - apy * abx;
    bool pass_a = (16 * ap2) < 61;
    bool pass_b = (16 * bp2) < 61;
    bool pass_m = (16 * cr * cr) < (61 * den);
    return (num <= 0) ? pass_a : (num >= den) ? pass_b : pass_m;
}

// Filter 4 pairs + issue predicated gathers. Returns pass mask.
__device__ __forceinline__ unsigned filter_and_gather(
        const unsigned* __restrict__ s,
        int4 v, int4 e0, int4 e1,
        float2* __restrict__ P, float2* __restrict__ A, float2* __restrict__ B) {
    const int iv[4] = { v.x,  v.y,  v.z,  v.w  };
    const int ia[4] = { e0.x, e0.y, e0.z, e0.w };
    const int ib[4] = { e1.x, e1.y, e1.z, e1.w };
    unsigned mask = 0;
    #pragma unroll
    for (int k = 0; k < 4; k++) {
        unsigned cp = qcode(s, iv[k]);
        unsigned ca = qcode(s, ia[k]);
        unsigned cb = qcode(s, ib[k]);
        if (cell_filter(cp, ca, cb)) mask |= (1u << k);
    }
    #pragma unroll
    for (int k = 0; k < 4; k++) {
        if (mask & (1u << k)) {
            P[k] = __ldg(&g_coords[iv[k]]);
            A[k] = __ldg(&g_coords[ia[k]]);
            B[k] = __ldg(&g_coords[ib[k]]);
        }
    }
    return mask;
}

// Branchless exact barrier for 4 gathered pairs.
__device__ __forceinline__ float compute4(unsigned mask,
        const float2* __restrict__ P, const float2* __restrict__ A,
        const float2* __restrict__ B) {
    float acc = 0.0f;
    #pragma unroll
    for (int k = 0; k < 4; k++) {
        float abx = B[k].x - A[k].x, aby = B[k].y - A[k].y;
        float apx = P[k].x - A[k].x, apy = P[k].y - A[k].y;
        float denom = abx * abx + aby * aby;
        float t = __saturatef(__fdividef(apx * abx + apy * aby,
                                         fmaxf(denom, EPSF)));
        float dx = apx - t * abx, dy = apy - t * aby;
        float d2 = dx * dx + dy * dy;
        float d2s = fmaxf(d2, EPSF);
        float g = d2s - DHAT2;
        float term = -(g * g) * __logf(d2s * (1.0f / DHAT2));
        bool valid = (mask & (1u << k)) && (d2 < DHAT2);
        acc += valid ? term : 0.0f;
    }
    return acc;
}

// ---------------------------------------------------------------- fused kernel
extern __shared__ unsigned s_qtab[];     // NWPAD words (~205 KB)

#define BLKT 640

__global__ void __launch_bounds__(BLKT, 1)
barrier_energy_fused(const int4* __restrict__ pv,
                     const int4* __restrict__ pe0,
                     const int4* __restrict__ pe1,
                     float* __restrict__ out) {
    // Stage quantized table via 128-bit loads.
    {
        const int4* src = reinterpret_cast<const int4*>(g_qtab);
        int4*       dst = reinterpret_cast<int4*>(s_qtab);
        for (int i = threadIdx.x; i < NWPAD / 4; i += blockDim.x)
            dst[i] = __ldg(&src[i]);
    }
    __syncthreads();

    float acc = 0.0f;
    const int nq = N_PAIRS / 4;
    const int stride = gridDim.x * blockDim.x;

    // ---- 2x-unrolled rotation-free pipeline ----
    // set0 / set1 alternate roles: one holds gathers in flight (consumed by
    // compute), the other holds freshly loaded indices (filtered next).
    int4 v0, w0, u0, v1, w1, u1;                 // index sets
    unsigned m0 = 0, m1 = 0;
    float2 P0[4], A0[4], B0[4], P1[4], A1[4], B1[4];
    #pragma unroll
    for (int k = 0; k < 4; k++) {
        P0[k] = A0[k] = B0[k] = make_float2(0.0f, 0.0f);
        P1[k] = A1[k] = B1[k] = make_float2(0.0f, 0.0f);
    }

    int q0 = blockIdx.x * blockDim.x + threadIdx.x;
    bool ok0 = q0 < nq;
    int q1 = q0 + stride;
    bool ok1 = q1 < nq;

    if (ok0) { v0 = __ldcs(&pv[q0]); w0 = __ldcs(&pe0[q0]); u0 = __ldcs(&pe1[q0]); }
    if (ok1) { v1 = __ldcs(&pv[q1]); w1 = __ldcs(&pe0[q1]); u1 = __ldcs(&pe1[q1]); }
    if (ok0) m0 = filter_and_gather(s_qtab, v0, w0, u0, P0, A0, B0);

    int qn = q1 + stride;
    while (ok0) {
        // ---- body A: load idx -> set0, gather set1, compute set0 ----
        bool okn = qn < nq;
        if (okn) { v0 = __ldcs(&pv[qn]); w0 = __ldcs(&pe0[qn]); u0 = __ldcs(&pe1[qn]); }
        if (ok1) m1 = filter_and_gather(s_qtab, v1, w1, u1, P1, A1, B1);
        acc += compute4(m0, P0, A0, B0);
        if (!ok1) break;
        qn += stride;

        // ---- body B: load idx -> set1, gather set0, compute set1 ----
        bool okm = qn < nq;
        ok0 = okn;
        if (okm) { v1 = __ldcs(&pv[qn]); w1 = __ldcs(&pe0[qn]); u1 = __ldcs(&pe1[qn]); }
        if (ok0) m0 = filter_and_gather(s_qtab, v0, w0, u0, P0, A0, B0);
        acc += compute4(m1, P1, A1, B1);
        if (!ok0) break;
        ok1 = okm;
        qn += stride;
    }

    // Block reduction; reuse head of s_qtab as scratch after sync.
    #pragma unroll
    for (int off = 16; off > 0; off >>= 1)
        acc += __shfl_down_sync(0xFFFFFFFFu, acc, off);

    __syncthreads();
    float* warp_sums = reinterpret_cast<float*>(s_qtab);
    int lane = threadIdx.x & 31;
    int wid  = threadIdx.x >> 5;
    if (lane == 0) warp_sums[wid] = acc;
    __syncthreads();

    if (wid == 0) {
        int nw = blockDim.x >> 5;   // 20
        float s = (lane < nw) ? warp_sums[lane] : 0.0f;
        #pragma unroll
        for (int off = 16; off > 0; off >>= 1)
            s += __shfl_down_sync(0xFFFFFFFFu, s, off);
        if (lane == 0) atomicAdd(out, s);
    }
}

// ---------------------------------------------------------------- launch
extern "C" void kernel_launch(void* const* d_in, const int* in_sizes, int n_in,
                              void* d_out, int out_size) {
    const float* Uu   = (const float*)d_in[0];
    const float* rest = (const float*)d_in[1];
    const int*   pv   = (const int*)d_in[2];
    const int*   pe0  = (const int*)d_in[3];
    const int*   pe1  = (const int*)d_in[4];
    float* out = (float*)d_out;

    setup_kernel<<<(NWPAD + 255) / 256, 256>>>(Uu, rest, out);

    const size_t smem_bytes = (size_t)NWPAD * sizeof(unsigned);   // ~205 KB
    cudaFuncSetAttribute(barrier_energy_fused,
                         cudaFuncAttributeMaxDynamicSharedMemorySize,
                         (int)smem_bytes);

    int nsm = 148;
    cudaDeviceGetAttribute(&nsm, cudaDevAttrMultiProcessorCount, 0);

    barrier_energy_fused<<<nsm, BLKT, smem_bytes>>>(
        (const int4*)pv, (const int4*)pe0, (const int4*)pe1, out);
}